// round 15
// baseline (speedup 1.0000x reference)
#include <cuda_runtime.h>
#include <cstdint>

// Problem constants: B=256, T=512, C=256, L=64, S=129
#define Bb 256
#define Tt 512
#define Cc 256
#define Ll 64
#define DEPTH 5            // cp.async ring depth (chunks of 8 timesteps)

// Scratch: per-lane label LINEAR-prob pairs, and blank linear probs.
static __device__ float2 g_pair[(size_t)Bb * Tt * 32];  // 33.5 MB  [b][t][lane]
static __device__ float  g_bl[(size_t)Bb * Tt];         // 512 KB   [b][t]
static __device__ float  g_loss[Bb];
static __device__ int    g_cnt = 0;

__device__ __forceinline__ float ex2f_(float x) {
    float y; asm("ex2.approx.ftz.f32 %0, %1;" : "=f"(y) : "f"(x)); return y;
}
__device__ __forceinline__ float lg2f_(float x) {
    float y; asm("lg2.approx.f32 %0, %1;" : "=f"(y) : "f"(x)); return y;
}
__device__ __forceinline__ void cpa16(uint32_t dst, const void* src) {
    asm volatile("cp.async.cg.shared.global [%0], [%1], 16;" :: "r"(dst), "l"(src));
}
__device__ __forceinline__ void cpa4(uint32_t dst, const void* src) {
    asm volatile("cp.async.ca.shared.global [%0], [%1], 4;" :: "r"(dst), "l"(src));
}

#define LOG2E  1.4426950408889634f
#define LN2    0.6931471805599453f

// ---------------------------------------------------------------------------
// Kernel 1: softmax + gather, 2 rows per warp (ILP-2, 4 LDG.128 in flight).
// Streaming loads keep the scratch L2-resident. Garbage labels zeroed.
// ---------------------------------------------------------------------------
__global__ void __launch_bounds__(256) k_logits(const float* __restrict__ logits,
                                                const int* __restrict__ targets,
                                                const int* __restrict__ tg_len) {
    __shared__ float rows[16][Cc];
    int wid  = threadIdx.x >> 5;
    int lane = threadIdx.x & 31;
    int w0 = blockIdx.x * 16 + wid * 2;  // rows w0, w0+1
    const float4* __restrict__ r4a = (const float4*)(logits + (size_t)w0 * Cc);
    const float4* __restrict__ r4b = (const float4*)(logits + (size_t)(w0 + 1) * Cc);

    float4 a0 = __ldcs(r4a + lane);
    float4 a1 = __ldcs(r4a + lane + 32);
    float4 b0 = __ldcs(r4b + lane);
    float4 b1 = __ldcs(r4b + lane + 32);
    ((float4*)rows[wid * 2    ])[lane]      = a0;
    ((float4*)rows[wid * 2    ])[lane + 32] = a1;
    ((float4*)rows[wid * 2 + 1])[lane]      = b0;
    ((float4*)rows[wid * 2 + 1])[lane + 32] = b1;

    float mA = fmaxf(fmaxf(fmaxf(a0.x, a0.y), fmaxf(a0.z, a0.w)),
                     fmaxf(fmaxf(a1.x, a1.y), fmaxf(a1.z, a1.w)));
    float mB = fmaxf(fmaxf(fmaxf(b0.x, b0.y), fmaxf(b0.z, b0.w)),
                     fmaxf(fmaxf(b1.x, b1.y), fmaxf(b1.z, b1.w)));
#pragma unroll
    for (int off = 16; off; off >>= 1) {
        mA = fmaxf(mA, __shfl_xor_sync(0xffffffffu, mA, off));
        mB = fmaxf(mB, __shfl_xor_sync(0xffffffffu, mB, off));
    }
    float m2A = mA * LOG2E, m2B = mB * LOG2E;
    float sA = ex2f_(a0.x * LOG2E - m2A) + ex2f_(a0.y * LOG2E - m2A)
             + ex2f_(a0.z * LOG2E - m2A) + ex2f_(a0.w * LOG2E - m2A)
             + ex2f_(a1.x * LOG2E - m2A) + ex2f_(a1.y * LOG2E - m2A)
             + ex2f_(a1.z * LOG2E - m2A) + ex2f_(a1.w * LOG2E - m2A);
    float sB = ex2f_(b0.x * LOG2E - m2B) + ex2f_(b0.y * LOG2E - m2B)
             + ex2f_(b0.z * LOG2E - m2B) + ex2f_(b0.w * LOG2E - m2B)
             + ex2f_(b1.x * LOG2E - m2B) + ex2f_(b1.y * LOG2E - m2B)
             + ex2f_(b1.z * LOG2E - m2B) + ex2f_(b1.w * LOG2E - m2B);
#pragma unroll
    for (int off = 16; off; off >>= 1) {
        sA += __shfl_xor_sync(0xffffffffu, sA, off);
        sB += __shfl_xor_sync(0xffffffffu, sB, off);
    }
    float baseA = m2A + lg2f_(sA);
    float baseB = m2B + lg2f_(sB);

    __syncwarp();
#pragma unroll
    for (int r = 0; r < 2; r++) {
        int w = w0 + r;
        int b = w >> 9;                  // T = 512
        float base = r ? baseB : baseA;
        int tl = tg_len[b];
        int2 tg2 = ((const int2*)(targets + b * Ll))[lane];
        float p1 = ex2f_(rows[wid * 2 + r][tg2.x] * LOG2E - base);
        float p3 = ex2f_(rows[wid * 2 + r][tg2.y] * LOG2E - base);
        if (2 * lane     >= tl) p1 = 0.0f;   // garbage label -> dead state
        if (2 * lane + 1 >= tl) p3 = 0.0f;
        g_pair[(size_t)w * 32 + lane] = make_float2(p1, p3);
        if (lane == 0)
            g_bl[w] = ex2f_(rows[wid * 2 + r][0] * LOG2E - base);
    }
}

// ---------------------------------------------------------------------------
// Kernel 2: CTC forward DP, LINEAR domain + pow2 rescale. TWO batches per
// warp (interleaved chains for ILP). cp.async smem ring, DEPTH chunks of 8
// steps per stream. Loss captured at t = Tin-1 mid-loop. Mean fused at end.
// ---------------------------------------------------------------------------
struct DPS { float a0, a1, a2, a3, aT; float s1, s3; int S; };

__global__ void __launch_bounds__(64) k_dp(const int* __restrict__ targets,
                                           const int* __restrict__ in_len,
                                           const int* __restrict__ tg_len,
                                           float* __restrict__ out) {
    __shared__ __align__(16) float2 ring_p[4][DEPTH][8][32];   // 40 KB
    __shared__ float ring_b[4][DEPTH][8];                      // 640 B
    __shared__ float As[2][132];
    __shared__ int   s_last;

    int tid  = threadIdx.x;
    int wid  = tid >> 5;
    int lane = tid & 31;
    int bA = blockIdx.x * 4 + wid * 2;
    int bB = bA + 1;
    int sAi = wid * 2, sBi = wid * 2 + 1;

    // per-batch static config
    DPS A, B;
    A.a0 = A.a1 = A.a2 = A.a3 = A.aT = 0.f; A.S = 0;
    B.a0 = B.a1 = B.a2 = B.a3 = B.aT = 0.f; B.S = 0;
    {
        int2 tga = ((const int2*)(targets + bA * Ll))[lane];
        int tp = __shfl_up_sync(0xffffffffu, tga.y, 1);
        A.s1 = ((lane > 0) && (tga.x != tp)) ? 1.0f : 0.0f;
        A.s3 = (tga.y != tga.x) ? 1.0f : 0.0f;
        int2 tgb = ((const int2*)(targets + bB * Ll))[lane];
        tp = __shfl_up_sync(0xffffffffu, tgb.y, 1);
        B.s1 = ((lane > 0) && (tgb.x != tp)) ? 1.0f : 0.0f;
        B.s3 = (tgb.y != tgb.x) ? 1.0f : 0.0f;
    }
    int TinA = in_len[bA], TinB = in_len[bB];
    int tlA  = tg_len[bA], tlB  = tg_len[bB];
    int capcA = (TinA - 1) >> 3, capkA = (TinA - 1) & 7;
    int capcB = (TinB - 1) >> 3, capkB = (TinB - 1) & 7;

    const char* __restrict__ pbA = (const char*)(g_pair + (size_t)bA * Tt * 32);
    const char* __restrict__ pbB = (const char*)(g_pair + (size_t)bB * Tt * 32);
    const float* __restrict__ bbA = g_bl + (size_t)bA * Tt;
    const float* __restrict__ bbB = g_bl + (size_t)bB * Tt;
    uint32_t pA_u32 = (uint32_t)__cvta_generic_to_shared(&ring_p[sAi][0][0][0]);
    uint32_t pB_u32 = (uint32_t)__cvta_generic_to_shared(&ring_p[sBi][0][0][0]);
    uint32_t bA_u32 = (uint32_t)__cvta_generic_to_shared(&ring_b[sAi][0][0]);
    uint32_t bB_u32 = (uint32_t)__cvta_generic_to_shared(&ring_b[sBi][0][0]);

#define PREF(pu, bu, pbase, bbase, cc_)                                  \
    {                                                                    \
        int cc = (cc_);                                                  \
        if (cc <= 63) {                                                  \
            const char* srcb = (pbase) + (size_t)cc * 2048;              \
            uint32_t dstb = (pu) + (uint32_t)(cc % DEPTH) * 2048;        \
            _Pragma("unroll")                                            \
            for (int i = 0; i < 4; i++)                                  \
                cpa16(dstb + i * 512 + lane * 16,                        \
                      srcb + i * 512 + lane * 16);                       \
            if (lane < 8)                                                \
                cpa4((bu) + (uint32_t)(cc % DEPTH) * 32 + lane * 4,      \
                     (const void*)((bbase) + cc * 8 + lane));            \
        }                                                                \
        asm volatile("cp.async.commit_group;");                          \
    }

#define STEP(D, lp, bl)                                                  \
    {                                                                    \
        float p3 = __shfl_up_sync(0xffffffffu, D.a3, 1);                 \
        p3 = (lane == 0) ? 0.0f : p3;                                    \
        float n0 = (D.a0 + p3) * (bl);                                   \
        float n1 = fmaf(D.s1, p3, D.a0 + D.a1) * (lp).x;                 \
        float n2 = (D.a1 + D.a2) * (bl);                                 \
        float n3 = fmaf(D.s3, D.a1, D.a2 + D.a3) * (lp).y;               \
        float nT = (D.a3 + D.aT) * (bl);                                 \
        D.a0 = n0; D.a1 = n1; D.a2 = n2; D.a3 = n3; D.aT = nT;           \
    }

#define RESCALE(D)                                                       \
    {                                                                    \
        float mx = fmaxf(fmaxf(fmaxf(D.a0, D.a1), fmaxf(D.a2, D.a3)), D.aT); \
        unsigned umx = __reduce_max_sync(0xffffffffu, __float_as_uint(mx)); \
        int ex = (int)(umx >> 23) & 255;                                 \
        int h  = 217 - ex;                                               \
        int h1 = h >> 1, h2 = h - h1;                                    \
        float fa_ = __uint_as_float((unsigned)(127 + h1) << 23);         \
        float fb_ = __uint_as_float((unsigned)(127 + h2) << 23);         \
        D.a0 *= fa_; D.a0 *= fb_; D.a1 *= fa_; D.a1 *= fb_;              \
        D.a2 *= fa_; D.a2 *= fb_; D.a3 *= fa_; D.a3 *= fb_;              \
        D.aT *= fa_; D.aT *= fb_;                                        \
        D.S += h;                                                        \
    }

#define CAPTURE(D, bidx, tl)                                             \
    {                                                                    \
        As[wid][lane * 4 + 0] = D.a0; As[wid][lane * 4 + 1] = D.a1;      \
        As[wid][lane * 4 + 2] = D.a2; As[wid][lane * 4 + 3] = D.a3;      \
        if (lane == 31) As[wid][128] = D.aT;                             \
        __syncwarp();                                                    \
        if (lane == 0) {                                                 \
            float fa = As[wid][2 * (tl)];                                \
            float fb = As[wid][2 * (tl) - 1];                            \
            float sum = fa + fb;                                         \
            float loss = LN2 * ((float)D.S - lg2f_(sum));                \
            if (!(loss <= 1e20f)) loss = 0.0f;                           \
            g_loss[bidx] = loss / (float)(tl);                           \
        }                                                                \
        __syncwarp();                                                    \
    }

#define LOADCHUNK(LP, BL, si, c7)                                        \
    {                                                                    \
        _Pragma("unroll")                                                \
        for (int k = 0; k < 8; k++) {                                    \
            LP[k] = ring_p[si][c7][k][lane];                             \
            BL[k] = ring_b[si][c7][k];                                   \
        }                                                                \
    }

    // prologue: fill both rings (interleaved commits: A0,B0,A1,B1,...)
#pragma unroll
    for (int c0 = 0; c0 < DEPTH; c0++) {
        PREF(pA_u32, bA_u32, pbA, bbA, c0);
        PREF(pB_u32, bB_u32, pbB, bbB, c0);
    }

    // chunk 0: init at t=0 then steps t=1..7 interleaved
    asm volatile("cp.async.wait_group %0;" :: "n"(2 * DEPTH - 2));
    __syncwarp();
    {
        float2 LPA[8], LPB[8]; float BLA[8], BLB[8];
        LOADCHUNK(LPA, BLA, sAi, 0);
        LOADCHUNK(LPB, BLB, sBi, 0);
        if (lane == 0) {
            A.a0 = BLA[0]; A.a1 = LPA[0].x;
            B.a0 = BLB[0]; B.a1 = LPB[0].x;
        }
#pragma unroll
        for (int k = 1; k < 8; k++) {
            STEP(A, LPA[k], BLA[k]);
            STEP(B, LPB[k], BLB[k]);
        }
        RESCALE(A); RESCALE(B);
    }
    PREF(pA_u32, bA_u32, pbA, bbA, DEPTH);
    PREF(pB_u32, bB_u32, pbB, bbB, DEPTH);

    int cmax = (capcA > capcB) ? capcA : capcB;
    for (int c = 1; c <= cmax; c++) {
        asm volatile("cp.async.wait_group %0;" :: "n"(2 * DEPTH - 2));
        __syncwarp();
        int c7 = c % DEPTH;
        bool doA = (c <= capcA), doB = (c <= capcB);
        bool hitA = (c == capcA), hitB = (c == capcB);
        if (doA && doB) {
            float2 LPA[8], LPB[8]; float BLA[8], BLB[8];
            LOADCHUNK(LPA, BLA, sAi, c7);
            LOADCHUNK(LPB, BLB, sBi, c7);
#pragma unroll
            for (int k = 0; k < 8; k++) {
                STEP(A, LPA[k], BLA[k]);
                STEP(B, LPB[k], BLB[k]);
                if (hitA && k == capkA) CAPTURE(A, bA, tlA);
                if (hitB && k == capkB) CAPTURE(B, bB, tlB);
            }
            RESCALE(A); RESCALE(B);
        } else if (doA) {
            float2 LPA[8]; float BLA[8];
            LOADCHUNK(LPA, BLA, sAi, c7);
#pragma unroll
            for (int k = 0; k < 8; k++) {
                STEP(A, LPA[k], BLA[k]);
                if (hitA && k == capkA) CAPTURE(A, bA, tlA);
            }
            RESCALE(A);
        } else {
            float2 LPB[8]; float BLB[8];
            LOADCHUNK(LPB, BLB, sBi, c7);
#pragma unroll
            for (int k = 0; k < 8; k++) {
                STEP(B, LPB[k], BLB[k]);
                if (hitB && k == capkB) CAPTURE(B, bB, tlB);
            }
            RESCALE(B);
        }
        PREF(pA_u32, bA_u32, pbA, bbA, c + DEPTH);
        PREF(pB_u32, bB_u32, pbB, bbB, c + DEPTH);
    }
    asm volatile("cp.async.wait_group 0;");
#undef STEP
#undef PREF
#undef RESCALE
#undef CAPTURE
#undef LOADCHUNK

    // ---- fused deterministic mean: last block to arrive reduces g_loss ----
    __syncthreads();
    __threadfence();
    if (tid == 0) {
        int rank = atomicAdd(&g_cnt, 1);
        s_last = (rank == (int)gridDim.x - 1) ? 1 : 0;
    }
    __syncthreads();
    if (s_last) {
        __threadfence();                 // acquire: see all g_loss writes
        __shared__ float sh[64];
        float v = g_loss[tid * 4 + 0] + g_loss[tid * 4 + 1]
                + g_loss[tid * 4 + 2] + g_loss[tid * 4 + 3];
        sh[tid] = v;
        __syncthreads();
#pragma unroll
        for (int off = 32; off; off >>= 1) {
            if (tid < off) sh[tid] += sh[tid + off];
            __syncthreads();
        }
        if (tid == 0) {
            out[0] = sh[0] * (1.0f / 256.0f);
            g_cnt = 0;                   // reset for next graph replay
        }
    }
}

extern "C" void kernel_launch(void* const* d_in, const int* in_sizes, int n_in,
                              void* d_out, int out_size) {
    const float* logits  = (const float*)d_in[0];   // [B,T,C] f32
    const int*   targets = (const int*)d_in[1];     // [B,L] i32
    const int*   in_len  = (const int*)d_in[2];     // [B] i32
    const int*   tg_len  = (const int*)d_in[3];     // [B] i32

    k_logits<<<(Bb * Tt) / 16, 256>>>(logits, targets, tg_len);
    k_dp<<<Bb / 4, 64>>>(targets, in_len, tg_len, (float*)d_out);
}